// round 15
// baseline (speedup 1.0000x reference)
#include <cuda_runtime.h>
#include <stdint.h>

#define BB 512
#define CH 16
#define HH 28
#define WW 28
#define HW 784
#define PH 14
#define PW 14
#define PHW 196
#define TT 8
#define NFC 100
#define NOUT 10
#define NPOOL (CH*PHW)  // 3136
#define NHALF (NPOOL/2) // 1568
#define N1 (BB*CH*HW)
#define PMAP 900        // padded 30x30 map
#define NT1P (BB*CH*PMAP)

typedef unsigned long long ull;

__device__ __align__(16) uint8_t g_t1p[NT1P];   // padded t1 maps, border=8
__device__ __align__(16) uint8_t g_tp[BB*NPOOL];
__device__ __align__(16) float   g_w1T[NPOOL*NFC];
__device__ int g_cnt1[9];
__device__ int g_cnt2[9];
__device__ int g_cnt3[9];
__device__ int g_cnt4[9];

// prep: zero counters + transpose w1 + prefill padded t1 maps with 8
// (borders stay 8 forever this launch; k1 overwrites interiors afterwards)
__global__ void k_prep(const float* __restrict__ w1) {
    int idx = blockIdx.x * 256 + threadIdx.x;
    if (idx < 9) { g_cnt1[idx] = 0; g_cnt2[idx] = 0; g_cnt3[idx] = 0; g_cnt4[idx] = 0; }
    if (idx < NFC * NPOOL) {
        int j = idx / NPOOL;
        int n = idx - j * NPOOL;
        g_w1T[n * NFC + j] = w1[idx];
    }
    if (idx < NT1P / 4) ((uint32_t*)g_t1p)[idx] = 0x08080808u;
}

// packed 16-bit x4 histogram helpers (buckets 0..7; bucket 8 dropped)
__device__ __forceinline__ void hist_add(ull& h0, ull& h1, int t) {
    if (t < 8) {
        if (t < 4) h0 += 1ull << (16 * t);
        else       h1 += 1ull << (16 * (t - 4));
    }
}
__device__ __forceinline__ void hist_flush_warp(ull h0, ull h1, int tid, int* sh) {
    if (tid < (int)(blockDim.x & ~31u)) {
#pragma unroll
        for (int off = 16; off; off >>= 1) {
            h0 += __shfl_down_sync(0xffffffffu, h0, off);
            h1 += __shfl_down_sync(0xffffffffu, h1, off);
        }
        if ((tid & 31) == 0) {
#pragma unroll
            for (int t = 0; t < 4; t++) {
                int c0 = (int)((h0 >> (16 * t)) & 0xffff);
                int c1 = (int)((h1 >> (16 * t)) & 0xffff);
                if (c0) atomicAdd(&sh[t], c0);
                if (c1) atomicAdd(&sh[t + 4], c1);
            }
        }
    } else {
#pragma unroll
        for (int t = 0; t < 4; t++) {
            int c0 = (int)((h0 >> (16 * t)) & 0xffff);
            int c1 = (int)((h1 >> (16 * t)) & 0xffff);
            if (c0) atomicAdd(&sh[t], c0);
            if (c1) atomicAdd(&sh[t + 4], c1);
        }
    }
}

// Kernel 1: static conv + OneSpikeIF t1 (padded layout). 1 pixel/thread,
// grid (BB, 2): block y-tile covers 14 rows. Prefill already done in k_prep.
__global__ void __launch_bounds__(392) k1_sconv(const float* __restrict__ x,
                                                const float* __restrict__ ws) {
    int b = blockIdx.x;
    __shared__ float sx[900];
    __shared__ float sw[CH * 9];
    __shared__ int sh[8];
    int tid = threadIdx.x;
    uint8_t* outp = g_t1p + b * CH * PMAP;
    for (int i = tid; i < 900; i += 392) sx[i] = 0.f;
    for (int i = tid; i < CH * 9; i += 392) sw[i] = ws[i];
    if (tid < 8) sh[tid] = 0;
    __syncthreads();
    for (int i = tid; i < HW; i += 392) {
        int y = i / WW, xx = i - y * WW;
        sx[(y + 1) * 30 + xx + 1] = x[b * HW + i];
    }
    __syncthreads();
    int p = blockIdx.y * 392 + tid;
    int y = p / WW, xx = p - y * WW;
    const float* xp = sx + (y + 1) * 30 + xx + 1;
    ull h0 = 0, h1 = 0;
#pragma unroll 1
    for (int o = 0; o < CH; o++) {
        const float* w = sw + o * 9;
        float acc = 0.f;
#pragma unroll
        for (int k = 0; k < 9; k++) {
            int dy = k / 3 - 1, dx = k % 3 - 1;
            acc += xp[dy * 30 + dx] * w[k];
        }
        float v = 0.f; int t1 = 8;
#pragma unroll
        for (int t = 0; t < TT; t++) { v += acc; if (v >= 1.f) { t1 = t; break; } }
        outp[o * PMAP + (y + 1) * 30 + xx + 1] = (uint8_t)t1;
        hist_add(h0, h1, t1);
    }
    hist_flush_warp(h0, h1, tid, sh);
    __syncthreads();
    if (tid < 8 && sh[tid]) atomicAdd(&g_cnt1[tid], sh[tid]);
}

// one t-slice of a tap: 1 setp + 4 predicated packed FMAs (4 oc-pairs)
#define TAP8(TLIT, A0, A1, A2, A3, W0, W1, W2, W3, TV, ONE)            \
    asm("{.reg .pred p; setp.le.s32 p, %9, " TLIT ";\n\t"              \
        "@p fma.rn.f32x2 %0, %4, %8, %0;\n\t"                          \
        "@p fma.rn.f32x2 %1, %5, %8, %1;\n\t"                          \
        "@p fma.rn.f32x2 %2, %6, %8, %2;\n\t"                          \
        "@p fma.rn.f32x2 %3, %7, %8, %3;}\n\t"                         \
        : "+l"(A0), "+l"(A1), "+l"(A2), "+l"(A3)                       \
        : "l"(W0), "l"(W1), "l"(W2), "l"(W3), "l"(ONE), "r"(TV))

#define TAP8U(A0, A1, A2, A3, W0, W1, W2, W3, ONE)                     \
    asm("fma.rn.f32x2 %0, %4, %8, %0;\n\t"                             \
        "fma.rn.f32x2 %1, %5, %8, %1;\n\t"                             \
        "fma.rn.f32x2 %2, %6, %8, %2;\n\t"                             \
        "fma.rn.f32x2 %3, %7, %8, %3;"                                 \
        : "+l"(A0), "+l"(A1), "+l"(A2), "+l"(A3)                       \
        : "l"(W0), "l"(W1), "l"(W2), "l"(W3), "l"(ONE))

#define DO_TAP_A(TV, WP)                                                    \
    if ((TV) < 4) {                                                         \
        const ulonglong2* _w = (const ulonglong2*)(WP);                     \
        ulonglong2 _wa = _w[0], _wb = _w[1];                                \
        TAP8("0", a0[0], a1[0], a2[0], a3[0], _wa.x, _wa.y, _wb.x, _wb.y, TV, ONE); \
        TAP8("1", a0[1], a1[1], a2[1], a3[1], _wa.x, _wa.y, _wb.x, _wb.y, TV, ONE); \
        TAP8("2", a0[2], a1[2], a2[2], a3[2], _wa.x, _wa.y, _wb.x, _wb.y, TV, ONE); \
        TAP8U(     a0[3], a1[3], a2[3], a3[3], _wa.x, _wa.y, _wb.x, _wb.y, ONE);    \
    }

#define DO_TAP_B(TV, WP)                                                    \
    if ((TV) < 8) {                                                         \
        const ulonglong2* _w = (const ulonglong2*)(WP);                     \
        ulonglong2 _wa = _w[0], _wb = _w[1];                                \
        TAP8("4", a0[0], a1[0], a2[0], a3[0], _wa.x, _wa.y, _wb.x, _wb.y, TV, ONE); \
        TAP8("5", a0[1], a1[1], a2[1], a3[1], _wa.x, _wa.y, _wb.x, _wb.y, TV, ONE); \
        TAP8("6", a0[2], a1[2], a2[2], a3[2], _wa.x, _wa.y, _wb.x, _wb.y, TV, ONE); \
        TAP8U(     a0[3], a1[3], a2[3], a3[3], _wa.x, _wa.y, _wb.x, _wb.y, ONE);    \
    }

#define DO_ROW_A(RO, WROW) do {                                             \
    int tv0 = tp[(RO) - 1], tv1 = tp[(RO)], tv2 = tp[(RO) + 1];             \
    DO_TAP_A(tv0, (WROW) + 0);                                              \
    DO_TAP_A(tv1, (WROW) + 8);                                              \
    DO_TAP_A(tv2, (WROW) + 16);                                             \
} while (0)

#define DO_ROW_B(RO, WROW) do {                                             \
    int tv0 = tp[(RO) - 1], tv1 = tp[(RO)], tv2 = tp[(RO) + 1];             \
    DO_TAP_B(tv0, (WROW) + 0);                                              \
    DO_TAP_B(tv1, (WROW) + 8);                                              \
    DO_TAP_B(tv2, (WROW) + 16);                                             \
} while (0)

#define EXTA(ARR, PR) do {                                                  \
    int lo = 8, hi = 8;                                                     \
    _Pragma("unroll")                                                       \
    for (int t = 3; t >= 0; t--) {                                          \
        ull v = ARR[t];                                                     \
        if (__uint_as_float((uint32_t)v) >= 1.f) lo = t;                    \
        if (__uint_as_float((uint32_t)(v >> 32)) >= 1.f) hi = t;            \
    }                                                                       \
    t2a_pack |= ((uint32_t)lo << (8 * (PR))) | ((uint32_t)hi << (8 * (PR) + 4)); \
} while (0)

#define EXTB(ARR, PR) do {                                                  \
    int lo = 8, hi = 8;                                                     \
    _Pragma("unroll")                                                       \
    for (int s = 3; s >= 0; s--) {                                          \
        ull v = ARR[s];                                                     \
        if (__uint_as_float((uint32_t)v) >= 1.f) lo = s + 4;                \
        if (__uint_as_float((uint32_t)(v >> 32)) >= 1.f) hi = s + 4;        \
    }                                                                       \
    int ta = (t2a_pack >> (8 * (PR))) & 15;                                 \
    int tb = (t2a_pack >> (8 * (PR) + 4)) & 15;                             \
    int flo = (ta < 8) ? ta : lo;                                           \
    int fhi = (tb < 8) ? tb : hi;                                           \
    int o = half * 8 + (PR) * 2;                                            \
    s2[o * 392 + tid] = (uint8_t)flo;       hist_add(h0, h1, flo);          \
    s2[(o + 1) * 392 + tid] = (uint8_t)fhi; hist_add(h0, h1, fhi);          \
} while (0)

// Kernel 2: conv2 all 8 timesteps, fused pool. t-split passes; 3 blocks/SM.
__global__ void __launch_bounds__(392, 3) k2_conv(const float* __restrict__ wc) {
    int b = blockIdx.x;
    int tid = threadIdx.x;
    int p = blockIdx.y * 392 + tid;
    __shared__ __align__(16) uint8_t st[CH * PMAP];
    __shared__ __align__(16) ull sw2[CH * 9 * 8];
    __shared__ uint8_t s2[CH * 392];
    __shared__ uint32_t sfm[CH * 30];
    __shared__ uint32_t sfm4[CH * 30];
    __shared__ int sh[8];

    if (tid < 8) sh[tid] = 0;
    {
        const uint4* src = (const uint4*)(g_t1p + b * CH * PMAP);
        uint4* dst = (uint4*)st;
        for (int i = tid; i < CH * PMAP / 16; i += 392) dst[i] = src[i];
    }
    for (int idx = tid; idx < CH * 9 * 8; idx += 392) {
        int pr = idx & 7;
        int ik = idx >> 3;
        uint32_t lo = __float_as_uint(wc[(2 * pr) * (CH * 9) + ik]);
        uint32_t hi = __float_as_uint(wc[(2 * pr + 1) * (CH * 9) + ik]);
        sw2[idx] = ((ull)hi << 32) | lo;
    }
    __syncthreads();
    for (int idx = tid; idx < CH * 30; idx += 392) {
        const uint8_t* row = st + (idx / 30) * PMAP + (idx % 30) * 30;
        uint32_t m8 = 0, m4 = 0;
#pragma unroll
        for (int c = 0; c < 30; c++) {
            int v = row[c];
            m8 |= (v < 8 ? 1u : 0u) << c;
            m4 |= (v < 4 ? 1u : 0u) << c;
        }
        sfm[idx] = m8;
        sfm4[idx] = m4;
    }
    __syncthreads();

    int y = p / WW, x = p - y * WW;
    const int q = (y + 1) * 30 + (x + 1);
    const ull ONE = 0x3f8000003f800000ull;
    ull h0 = 0, h1 = 0;

    ull rm8 = 0, rm4 = 0;
#pragma unroll
    for (int i = 0; i < CH; i++) {
        uint32_t a0m = (sfm[i * 30 + y] >> x) & 7u;
        uint32_t a1m = (sfm[i * 30 + y + 1] >> x) & 7u;
        uint32_t a2m = (sfm[i * 30 + y + 2] >> x) & 7u;
        rm8 |= (ull)((a0m ? 1u : 0u) | (a1m ? 2u : 0u) | (a2m ? 4u : 0u)) << (3 * i);
        uint32_t b0m = (sfm4[i * 30 + y] >> x) & 7u;
        uint32_t b1m = (sfm4[i * 30 + y + 1] >> x) & 7u;
        uint32_t b2m = (sfm4[i * 30 + y + 2] >> x) & 7u;
        rm4 |= (ull)((b0m ? 1u : 0u) | (b1m ? 2u : 0u) | (b2m ? 4u : 0u)) << (3 * i);
    }

    const unsigned am = (tid >= 384) ? 0x000000ffu : 0xffffffffu;
    if (__all_sync(am, rm8 == 0ull)) {
#pragma unroll
        for (int o = 0; o < CH; o++) s2[o * 392 + tid] = 8;
    } else {
        for (int half = 0; half < 2; half++) {
            uint32_t t2a_pack = 0;
            {   // pass A: slices t=0..3, early taps (tv<4) only
                ull a0[4], a1[4], a2[4], a3[4];
#pragma unroll
                for (int s = 0; s < 4; s++) { a0[s] = 0; a1[s] = 0; a2[s] = 0; a3[s] = 0; }
#pragma unroll 1
                for (int i = 0; i < CH; i++) {
                    unsigned g = (unsigned)(rm4 >> (3 * i)) & 7u;
                    if (!g) continue;
                    const uint8_t* tp = st + i * PMAP + q;
                    const ull* wi = sw2 + i * 72 + half * 4;
                    if (g & 1u) DO_ROW_A(-30, wi + 0);
                    if (g & 2u) DO_ROW_A(0,   wi + 24);
                    if (g & 4u) DO_ROW_A(30,  wi + 48);
                }
                EXTA(a0, 0); EXTA(a1, 1); EXTA(a2, 2); EXTA(a3, 3);
            }
            {   // pass B: slices t=4..7, all fired taps (tv<8)
                ull a0[4], a1[4], a2[4], a3[4];
#pragma unroll
                for (int s = 0; s < 4; s++) { a0[s] = 0; a1[s] = 0; a2[s] = 0; a3[s] = 0; }
#pragma unroll 1
                for (int i = 0; i < CH; i++) {
                    unsigned g = (unsigned)(rm8 >> (3 * i)) & 7u;
                    if (!g) continue;
                    const uint8_t* tp = st + i * PMAP + q;
                    const ull* wi = sw2 + i * 72 + half * 4;
                    if (g & 1u) DO_ROW_B(-30, wi + 0);
                    if (g & 2u) DO_ROW_B(0,   wi + 24);
                    if (g & 4u) DO_ROW_B(30,  wi + 48);
                }
                EXTB(a0, 0); EXTB(a1, 1); EXTB(a2, 2); EXTB(a3, 3);
            }
        }
    }
    hist_flush_warp(h0, h1, tid, sh);
    __syncthreads();
    for (int idx = tid; idx < CH * 7 * PW; idx += 392) {
        int X = idx % PW;
        int r = idx / PW;
        int Yl = r % 7;
        int oc = r / 7;
        const uint8_t* base = s2 + oc * 392 + (Yl * 2) * WW + X * 2;
        int m = min(min((int)base[0], (int)base[1]),
                    min((int)base[WW], (int)base[WW + 1]));
        g_tp[b * NPOOL + oc * PHW + (blockIdx.y * 7 + Yl) * PW + X] = (uint8_t)m;
    }
    if (tid < 8 && sh[tid]) atomicAdd(&g_cnt2[tid], sh[tid]);
}

// Kernel 45 (frozen): 2 batches x 2 n-halves per 512-thread block.
__global__ void __launch_bounds__(512) k45(const float* __restrict__ w2,
                                           float* __restrict__ out) {
    const ull K8 = 0x0808080808080808ull;
    int b0 = blockIdx.x * 2;
    int tid = threadIdx.x;
    int bb = tid >> 8;
    int half = (tid >> 7) & 1;
    int j = tid & 127;
    __shared__ uint8_t stp[2 * NPOOL];
    __shared__ float sw2s[NOUT * NFC];
    __shared__ float sS[2][NFC][8];
    __shared__ uint8_t s3[2 * NFC];
    __shared__ int sh3[8], sh4[8];
    {
        const uint4* src = (const uint4*)(g_tp + b0 * NPOOL);
        for (int i = tid; i < 2 * NPOOL / 16; i += 512) ((uint4*)stp)[i] = src[i];
    }
    for (int i = tid; i < NOUT * NFC; i += 512) sw2s[i] = w2[i];
    if (tid < 8) { sh3[tid] = 0; sh4[tid] = 0; }
    __syncthreads();

    float S[8] = {0.f, 0.f, 0.f, 0.f, 0.f, 0.f, 0.f, 0.f};
    if (j < NFC) {
        const uint8_t* tb = stp + bb * NPOOL;
        const int nbeg = half * NHALF, nend = nbeg + NHALF;
        const float* wcol = g_w1T + j;
#pragma unroll 1
        for (int n0 = nbeg; n0 < nend; n0 += 16) {
            ull tvA = *(const ull*)(tb + n0);
            ull tvB = *(const ull*)(tb + n0 + 8);
            if (tvA == K8 && tvB == K8) continue;
            float w[16];
#pragma unroll
            for (int i = 0; i < 16; i++) w[i] = __ldg(wcol + (n0 + i) * NFC);
#pragma unroll
            for (int i = 0; i < 16; i++) {
                int tv = (int)((i < 8 ? (tvA >> (8 * i)) : (tvB >> (8 * (i - 8)))) & 0xff);
                if (tv < 8) {
                    switch (tv) {
                        case 0: S[0] += w[i]; break;
                        case 1: S[1] += w[i]; break;
                        case 2: S[2] += w[i]; break;
                        case 3: S[3] += w[i]; break;
                        case 4: S[4] += w[i]; break;
                        case 5: S[5] += w[i]; break;
                        case 6: S[6] += w[i]; break;
                        case 7: S[7] += w[i]; break;
                    }
                }
            }
        }
    }
    if (half == 1 && j < NFC) {
#pragma unroll
        for (int t = 0; t < 8; t++) sS[bb][j][t] = S[t];
    }
    __syncthreads();
    int t3 = 8;
    if (half == 0 && j < NFC) {
        float Cv = 0.f;
#pragma unroll
        for (int t = 0; t < TT; t++) {
            Cv += S[t] + sS[bb][j][t];
            if (t3 == 8 && Cv >= 1.f) t3 = t;
        }
        s3[bb * NFC + j] = (uint8_t)t3;
    }
    if (half == 0) {
#pragma unroll
        for (int t = 0; t < 8; t++) {
            unsigned bal = __ballot_sync(0xffffffffu, (j < NFC) && (t3 == t));
            if ((tid & 31) == 0 && bal) atomicAdd(&sh3[t], __popc(bal));
        }
    }
    __syncthreads();
    if (half == 0 && j < NOUT) {
        int b = b0 + bb;
        const uint8_t* sb = s3 + bb * NFC;
        float O[8] = {0.f, 0.f, 0.f, 0.f, 0.f, 0.f, 0.f, 0.f};
        for (int jj = 0; jj < NFC; jj++) {
            int tv = sb[jj];
            if (tv < 8) {
                float w = sw2s[j * NFC + jj];
                switch (tv) {
                    case 0: O[0] += w; break;
                    case 1: O[1] += w; break;
                    case 2: O[2] += w; break;
                    case 3: O[3] += w; break;
                    case 4: O[4] += w; break;
                    case 5: O[5] += w; break;
                    case 6: O[6] += w; break;
                    case 7: O[7] += w; break;
                }
            }
        }
        float v = 0.f; int first = 8;
#pragma unroll
        for (int t = 0; t < TT; t++) {
            v += O[t];
            if (v >= 1.f) {
                v = 0.f;
                if (first == 8) first = t;
                atomicAdd(&sh4[t], 1);
            }
        }
        out[b * NOUT + j] = (first < 8) ? (float)(TT - first) / (float)TT : 0.f;
    }
    __syncthreads();
    if (tid < 8) {
        if (sh3[tid]) atomicAdd(&g_cnt3[tid], sh3[tid]);
        if (sh4[tid]) atomicAdd(&g_cnt4[tid], sh4[tid]);
    }
}

__global__ void k6_final(float* __restrict__ out, int write_reg) {
    if (threadIdx.x == 0 && write_reg) {
        float m1 = 0.f, m2 = 0.f, m3 = 0.f, m4 = 0.f;
        for (int t = 0; t < TT; t++) {
            m1 = fmaxf(m1, (float)g_cnt1[t] / (float)N1);
            m2 = fmaxf(m2, (float)g_cnt2[t] / (float)N1);
            m3 = fmaxf(m3, (float)g_cnt3[t] / (float)(BB * NFC));
            m4 = fmaxf(m4, (float)g_cnt4[t] / (float)(BB * NOUT));
        }
        out[BB * NOUT] = m1 + m2 + m3 + m4;
    }
}

extern "C" void kernel_launch(void* const* d_in, const int* in_sizes, int n_in,
                              void* d_out, int out_size) {
    const float* x  = (const float*)d_in[0];
    const float* ws = (const float*)d_in[1];
    const float* wc = (const float*)d_in[2];
    const float* w1 = (const float*)d_in[3];
    const float* w2 = (const float*)d_in[4];
    float* out = (float*)d_out;

    k_prep<<<(NT1P / 4 + 255) / 256, 256>>>(w1);
    {
        dim3 g1(BB, 2);
        k1_sconv<<<g1, 392>>>(x, ws);
    }
    {
        dim3 g(BB, 2);
        k2_conv<<<g, 392>>>(wc);
    }
    k45<<<BB / 2, 512>>>(w2, out);
    k6_final<<<1, 1>>>(out, (out_size > BB * NOUT) ? 1 : 0);
}

// round 16
// speedup vs baseline: 1.1005x; 1.1005x over previous
#include <cuda_runtime.h>
#include <stdint.h>

#define BB 512
#define CH 16
#define HH 28
#define WW 28
#define HW 784
#define PH 14
#define PW 14
#define PHW 196
#define TT 8
#define NFC 100
#define NOUT 10
#define NPOOL (CH*PHW)  // 3136
#define NHALF (NPOOL/2) // 1568
#define N1 (BB*CH*HW)
#define PMAP 900        // padded 30x30 map
#define NT1P (BB*CH*PMAP)

typedef unsigned long long ull;

__device__ __align__(16) uint8_t g_t1p[NT1P];   // padded t1 maps, border=8
__device__ __align__(16) uint8_t g_tp[BB*NPOOL];
__device__ __align__(16) float   g_w1T[NPOOL*NFC];
__device__ int g_cnt1[9];
__device__ int g_cnt2[9];
__device__ int g_cnt3[9];
__device__ int g_cnt4[9];

// prep: zero counters + transpose w1 + prefill padded t1 maps with 8
__global__ void k_prep(const float* __restrict__ w1) {
    int idx = blockIdx.x * 256 + threadIdx.x;
    if (idx < 9) { g_cnt1[idx] = 0; g_cnt2[idx] = 0; g_cnt3[idx] = 0; g_cnt4[idx] = 0; }
    if (idx < NFC * NPOOL) {
        int j = idx / NPOOL;
        int n = idx - j * NPOOL;
        g_w1T[n * NFC + j] = w1[idx];
    }
    if (idx < NT1P / 4) ((uint32_t*)g_t1p)[idx] = 0x08080808u;
}

// packed 16-bit x4 histogram helpers (buckets 0..7; bucket 8 dropped)
__device__ __forceinline__ void hist_add(ull& h0, ull& h1, int t) {
    if (t < 8) {
        if (t < 4) h0 += 1ull << (16 * t);
        else       h1 += 1ull << (16 * (t - 4));
    }
}
__device__ __forceinline__ void hist_flush_warp(ull h0, ull h1, int tid, int* sh) {
    if (tid < (int)(blockDim.x & ~31u)) {
#pragma unroll
        for (int off = 16; off; off >>= 1) {
            h0 += __shfl_down_sync(0xffffffffu, h0, off);
            h1 += __shfl_down_sync(0xffffffffu, h1, off);
        }
        if ((tid & 31) == 0) {
#pragma unroll
            for (int t = 0; t < 4; t++) {
                int c0 = (int)((h0 >> (16 * t)) & 0xffff);
                int c1 = (int)((h1 >> (16 * t)) & 0xffff);
                if (c0) atomicAdd(&sh[t], c0);
                if (c1) atomicAdd(&sh[t + 4], c1);
            }
        }
    } else {
#pragma unroll
        for (int t = 0; t < 4; t++) {
            int c0 = (int)((h0 >> (16 * t)) & 0xffff);
            int c1 = (int)((h1 >> (16 * t)) & 0xffff);
            if (c0) atomicAdd(&sh[t], c0);
            if (c1) atomicAdd(&sh[t + 4], c1);
        }
    }
}

// Kernel 1 (R14 structure): static conv + OneSpikeIF t1, padded layout.
// Prefill already done by k_prep; only interior written here.
__global__ void __launch_bounds__(392) k1_sconv(const float* __restrict__ x,
                                                const float* __restrict__ ws) {
    int b = blockIdx.x;
    __shared__ float sx[900];
    __shared__ float sw[CH * 9];
    __shared__ int sh[8];
    int tid = threadIdx.x;
    uint8_t* outp = g_t1p + b * CH * PMAP;
    for (int i = tid; i < 900; i += 392) sx[i] = 0.f;
    for (int i = tid; i < CH * 9; i += 392) sw[i] = ws[i];
    if (tid < 8) sh[tid] = 0;
    __syncthreads();
    for (int i = tid; i < HW; i += 392) {
        int y = i / WW, xx = i - y * WW;
        sx[(y + 1) * 30 + xx + 1] = x[b * HW + i];
    }
    __syncthreads();
    ull h0 = 0, h1 = 0;
    for (int o = 0; o < CH; o++) {
        const float* w = sw + o * 9;
        for (int p = tid; p < HW; p += 392) {
            int y = p / WW, xx = p - y * WW;
            const float* xp = sx + (y + 1) * 30 + xx + 1;
            float acc = 0.f;
#pragma unroll
            for (int k = 0; k < 9; k++) {
                int dy = k / 3 - 1, dx = k % 3 - 1;
                acc += xp[dy * 30 + dx] * w[k];
            }
            float v = 0.f; int t1 = 8;
#pragma unroll
            for (int t = 0; t < TT; t++) { v += acc; if (v >= 1.f) { t1 = t; break; } }
            outp[o * PMAP + (y + 1) * 30 + xx + 1] = (uint8_t)t1;
            hist_add(h0, h1, t1);
        }
    }
    hist_flush_warp(h0, h1, tid, sh);
    __syncthreads();
    if (tid < 8 && sh[tid]) atomicAdd(&g_cnt1[tid], sh[tid]);
}

// one t-slice of a tap: 1 setp + 4 predicated packed FMAs (4 oc-pairs)
#define TAP8(TLIT, A0, A1, A2, A3, W0, W1, W2, W3, TV, ONE)            \
    asm("{.reg .pred p; setp.le.s32 p, %9, " TLIT ";\n\t"              \
        "@p fma.rn.f32x2 %0, %4, %8, %0;\n\t"                          \
        "@p fma.rn.f32x2 %1, %5, %8, %1;\n\t"                          \
        "@p fma.rn.f32x2 %2, %6, %8, %2;\n\t"                          \
        "@p fma.rn.f32x2 %3, %7, %8, %3;}\n\t"                         \
        : "+l"(A0), "+l"(A1), "+l"(A2), "+l"(A3)                       \
        : "l"(W0), "l"(W1), "l"(W2), "l"(W3), "l"(ONE), "r"(TV))

#define TAP8U(A0, A1, A2, A3, W0, W1, W2, W3, ONE)                     \
    asm("fma.rn.f32x2 %0, %4, %8, %0;\n\t"                             \
        "fma.rn.f32x2 %1, %5, %8, %1;\n\t"                             \
        "fma.rn.f32x2 %2, %6, %8, %2;\n\t"                             \
        "fma.rn.f32x2 %3, %7, %8, %3;"                                 \
        : "+l"(A0), "+l"(A1), "+l"(A2), "+l"(A3)                       \
        : "l"(W0), "l"(W1), "l"(W2), "l"(W3), "l"(ONE))

#define DO_TAP_A(TV, WP)                                                    \
    if ((TV) < 4) {                                                         \
        const ulonglong2* _w = (const ulonglong2*)(WP);                     \
        ulonglong2 _wa = _w[0], _wb = _w[1];                                \
        TAP8("0", a0[0], a1[0], a2[0], a3[0], _wa.x, _wa.y, _wb.x, _wb.y, TV, ONE); \
        TAP8("1", a0[1], a1[1], a2[1], a3[1], _wa.x, _wa.y, _wb.x, _wb.y, TV, ONE); \
        TAP8("2", a0[2], a1[2], a2[2], a3[2], _wa.x, _wa.y, _wb.x, _wb.y, TV, ONE); \
        TAP8U(     a0[3], a1[3], a2[3], a3[3], _wa.x, _wa.y, _wb.x, _wb.y, ONE);    \
    }

#define DO_TAP_B(TV, WP)                                                    \
    if ((TV) < 8) {                                                         \
        const ulonglong2* _w = (const ulonglong2*)(WP);                     \
        ulonglong2 _wa = _w[0], _wb = _w[1];                                \
        TAP8("4", a0[0], a1[0], a2[0], a3[0], _wa.x, _wa.y, _wb.x, _wb.y, TV, ONE); \
        TAP8("5", a0[1], a1[1], a2[1], a3[1], _wa.x, _wa.y, _wb.x, _wb.y, TV, ONE); \
        TAP8("6", a0[2], a1[2], a2[2], a3[2], _wa.x, _wa.y, _wb.x, _wb.y, TV, ONE); \
        TAP8U(     a0[3], a1[3], a2[3], a3[3], _wa.x, _wa.y, _wb.x, _wb.y, ONE);    \
    }

#define DO_ROW_A(RO, WROW) do {                                             \
    int tv0 = tp[(RO) - 1], tv1 = tp[(RO)], tv2 = tp[(RO) + 1];             \
    DO_TAP_A(tv0, (WROW) + 0);                                              \
    DO_TAP_A(tv1, (WROW) + 8);                                              \
    DO_TAP_A(tv2, (WROW) + 16);                                             \
} while (0)

#define DO_ROW_B(RO, WROW) do {                                             \
    int tv0 = tp[(RO) - 1], tv1 = tp[(RO)], tv2 = tp[(RO) + 1];             \
    DO_TAP_B(tv0, (WROW) + 0);                                              \
    DO_TAP_B(tv1, (WROW) + 8);                                              \
    DO_TAP_B(tv2, (WROW) + 16);                                             \
} while (0)

#define EXTA(ARR, PR) do {                                                  \
    int lo = 8, hi = 8;                                                     \
    _Pragma("unroll")                                                       \
    for (int t = 3; t >= 0; t--) {                                          \
        ull v = ARR[t];                                                     \
        if (__uint_as_float((uint32_t)v) >= 1.f) lo = t;                    \
        if (__uint_as_float((uint32_t)(v >> 32)) >= 1.f) hi = t;            \
    }                                                                       \
    t2a_pack |= ((uint32_t)lo << (8 * (PR))) | ((uint32_t)hi << (8 * (PR) + 4)); \
} while (0)

#define EXTB(ARR, PR) do {                                                  \
    int lo = 8, hi = 8;                                                     \
    _Pragma("unroll")                                                       \
    for (int s = 3; s >= 0; s--) {                                          \
        ull v = ARR[s];                                                     \
        if (__uint_as_float((uint32_t)v) >= 1.f) lo = s + 4;                \
        if (__uint_as_float((uint32_t)(v >> 32)) >= 1.f) hi = s + 4;        \
    }                                                                       \
    int ta = (t2a_pack >> (8 * (PR))) & 15;                                 \
    int tb = (t2a_pack >> (8 * (PR) + 4)) & 15;                             \
    int flo = (ta < 8) ? ta : lo;                                           \
    int fhi = (tb < 8) ? tb : hi;                                           \
    int o = half * 8 + (PR) * 2;                                            \
    s2[o * 392 + tid] = (uint8_t)flo;       hist_add(h0, h1, flo);          \
    s2[(o + 1) * 392 + tid] = (uint8_t)fhi; hist_add(h0, h1, fhi);          \
} while (0)

// Kernel 2 (R14 frozen): conv2 all 8 timesteps, fused pool, t-split passes.
__global__ void __launch_bounds__(392, 2) k2_conv(const float* __restrict__ wc) {
    int b = blockIdx.x;
    int tid = threadIdx.x;
    int p = blockIdx.y * 392 + tid;
    __shared__ __align__(16) uint8_t st[CH * PMAP];
    __shared__ __align__(16) ull sw2[CH * 9 * 8];
    __shared__ uint8_t s2[CH * 392];
    __shared__ uint32_t sfm[CH * 30];
    __shared__ uint32_t sfm4[CH * 30];
    __shared__ int sh[8];

    if (tid < 8) sh[tid] = 0;
    {
        const uint4* src = (const uint4*)(g_t1p + b * CH * PMAP);
        uint4* dst = (uint4*)st;
        for (int i = tid; i < CH * PMAP / 16; i += 392) dst[i] = src[i];
    }
    for (int idx = tid; idx < CH * 9 * 8; idx += 392) {
        int pr = idx & 7;
        int ik = idx >> 3;
        uint32_t lo = __float_as_uint(wc[(2 * pr) * (CH * 9) + ik]);
        uint32_t hi = __float_as_uint(wc[(2 * pr + 1) * (CH * 9) + ik]);
        sw2[idx] = ((ull)hi << 32) | lo;
    }
    __syncthreads();
    for (int idx = tid; idx < CH * 30; idx += 392) {
        const uint8_t* row = st + (idx / 30) * PMAP + (idx % 30) * 30;
        uint32_t m8 = 0, m4 = 0;
#pragma unroll
        for (int c = 0; c < 30; c++) {
            int v = row[c];
            m8 |= (v < 8 ? 1u : 0u) << c;
            m4 |= (v < 4 ? 1u : 0u) << c;
        }
        sfm[idx] = m8;
        sfm4[idx] = m4;
    }
    __syncthreads();

    int y = p / WW, x = p - y * WW;
    const int q = (y + 1) * 30 + (x + 1);
    const ull ONE = 0x3f8000003f800000ull;
    ull h0 = 0, h1 = 0;

    ull rm8 = 0, rm4 = 0;
#pragma unroll
    for (int i = 0; i < CH; i++) {
        uint32_t a0m = (sfm[i * 30 + y] >> x) & 7u;
        uint32_t a1m = (sfm[i * 30 + y + 1] >> x) & 7u;
        uint32_t a2m = (sfm[i * 30 + y + 2] >> x) & 7u;
        rm8 |= (ull)((a0m ? 1u : 0u) | (a1m ? 2u : 0u) | (a2m ? 4u : 0u)) << (3 * i);
        uint32_t b0m = (sfm4[i * 30 + y] >> x) & 7u;
        uint32_t b1m = (sfm4[i * 30 + y + 1] >> x) & 7u;
        uint32_t b2m = (sfm4[i * 30 + y + 2] >> x) & 7u;
        rm4 |= (ull)((b0m ? 1u : 0u) | (b1m ? 2u : 0u) | (b2m ? 4u : 0u)) << (3 * i);
    }

    const unsigned am = (tid >= 384) ? 0x000000ffu : 0xffffffffu;
    if (__all_sync(am, rm8 == 0ull)) {
#pragma unroll
        for (int o = 0; o < CH; o++) s2[o * 392 + tid] = 8;
    } else {
        for (int half = 0; half < 2; half++) {
            uint32_t t2a_pack = 0;
            {   // pass A: slices t=0..3, early taps (tv<4) only
                ull a0[4], a1[4], a2[4], a3[4];
#pragma unroll
                for (int s = 0; s < 4; s++) { a0[s] = 0; a1[s] = 0; a2[s] = 0; a3[s] = 0; }
#pragma unroll 1
                for (int i = 0; i < CH; i++) {
                    unsigned g = (unsigned)(rm4 >> (3 * i)) & 7u;
                    if (!g) continue;
                    const uint8_t* tp = st + i * PMAP + q;
                    const ull* wi = sw2 + i * 72 + half * 4;
                    if (g & 1u) DO_ROW_A(-30, wi + 0);
                    if (g & 2u) DO_ROW_A(0,   wi + 24);
                    if (g & 4u) DO_ROW_A(30,  wi + 48);
                }
                EXTA(a0, 0); EXTA(a1, 1); EXTA(a2, 2); EXTA(a3, 3);
            }
            {   // pass B: slices t=4..7, all fired taps (tv<8)
                ull a0[4], a1[4], a2[4], a3[4];
#pragma unroll
                for (int s = 0; s < 4; s++) { a0[s] = 0; a1[s] = 0; a2[s] = 0; a3[s] = 0; }
#pragma unroll 1
                for (int i = 0; i < CH; i++) {
                    unsigned g = (unsigned)(rm8 >> (3 * i)) & 7u;
                    if (!g) continue;
                    const uint8_t* tp = st + i * PMAP + q;
                    const ull* wi = sw2 + i * 72 + half * 4;
                    if (g & 1u) DO_ROW_B(-30, wi + 0);
                    if (g & 2u) DO_ROW_B(0,   wi + 24);
                    if (g & 4u) DO_ROW_B(30,  wi + 48);
                }
                EXTB(a0, 0); EXTB(a1, 1); EXTB(a2, 2); EXTB(a3, 3);
            }
        }
    }
    hist_flush_warp(h0, h1, tid, sh);
    __syncthreads();
    for (int idx = tid; idx < CH * 7 * PW; idx += 392) {
        int X = idx % PW;
        int r = idx / PW;
        int Yl = r % 7;
        int oc = r / 7;
        const uint8_t* base = s2 + oc * 392 + (Yl * 2) * WW + X * 2;
        int m = min(min((int)base[0], (int)base[1]),
                    min((int)base[WW], (int)base[WW + 1]));
        g_tp[b * NPOOL + oc * PHW + (blockIdx.y * 7 + Yl) * PW + X] = (uint8_t)m;
    }
    if (tid < 8 && sh[tid]) atomicAdd(&g_cnt2[tid], sh[tid]);
}

// Kernel 45 (frozen): 2 batches x 2 n-halves per 512-thread block.
__global__ void __launch_bounds__(512) k45(const float* __restrict__ w2,
                                           float* __restrict__ out) {
    const ull K8 = 0x0808080808080808ull;
    int b0 = blockIdx.x * 2;
    int tid = threadIdx.x;
    int bb = tid >> 8;
    int half = (tid >> 7) & 1;
    int j = tid & 127;
    __shared__ uint8_t stp[2 * NPOOL];
    __shared__ float sw2s[NOUT * NFC];
    __shared__ float sS[2][NFC][8];
    __shared__ uint8_t s3[2 * NFC];
    __shared__ int sh3[8], sh4[8];
    {
        const uint4* src = (const uint4*)(g_tp + b0 * NPOOL);
        for (int i = tid; i < 2 * NPOOL / 16; i += 512) ((uint4*)stp)[i] = src[i];
    }
    for (int i = tid; i < NOUT * NFC; i += 512) sw2s[i] = w2[i];
    if (tid < 8) { sh3[tid] = 0; sh4[tid] = 0; }
    __syncthreads();

    float S[8] = {0.f, 0.f, 0.f, 0.f, 0.f, 0.f, 0.f, 0.f};
    if (j < NFC) {
        const uint8_t* tb = stp + bb * NPOOL;
        const int nbeg = half * NHALF, nend = nbeg + NHALF;
        const float* wcol = g_w1T + j;
#pragma unroll 1
        for (int n0 = nbeg; n0 < nend; n0 += 16) {
            ull tvA = *(const ull*)(tb + n0);
            ull tvB = *(const ull*)(tb + n0 + 8);
            if (tvA == K8 && tvB == K8) continue;
            float w[16];
#pragma unroll
            for (int i = 0; i < 16; i++) w[i] = __ldg(wcol + (n0 + i) * NFC);
#pragma unroll
            for (int i = 0; i < 16; i++) {
                int tv = (int)((i < 8 ? (tvA >> (8 * i)) : (tvB >> (8 * (i - 8)))) & 0xff);
                if (tv < 8) {
                    switch (tv) {
                        case 0: S[0] += w[i]; break;
                        case 1: S[1] += w[i]; break;
                        case 2: S[2] += w[i]; break;
                        case 3: S[3] += w[i]; break;
                        case 4: S[4] += w[i]; break;
                        case 5: S[5] += w[i]; break;
                        case 6: S[6] += w[i]; break;
                        case 7: S[7] += w[i]; break;
                    }
                }
            }
        }
    }
    if (half == 1 && j < NFC) {
#pragma unroll
        for (int t = 0; t < 8; t++) sS[bb][j][t] = S[t];
    }
    __syncthreads();
    int t3 = 8;
    if (half == 0 && j < NFC) {
        float Cv = 0.f;
#pragma unroll
        for (int t = 0; t < TT; t++) {
            Cv += S[t] + sS[bb][j][t];
            if (t3 == 8 && Cv >= 1.f) t3 = t;
        }
        s3[bb * NFC + j] = (uint8_t)t3;
    }
    if (half == 0) {
#pragma unroll
        for (int t = 0; t < 8; t++) {
            unsigned bal = __ballot_sync(0xffffffffu, (j < NFC) && (t3 == t));
            if ((tid & 31) == 0 && bal) atomicAdd(&sh3[t], __popc(bal));
        }
    }
    __syncthreads();
    if (half == 0 && j < NOUT) {
        int b = b0 + bb;
        const uint8_t* sb = s3 + bb * NFC;
        float O[8] = {0.f, 0.f, 0.f, 0.f, 0.f, 0.f, 0.f, 0.f};
        for (int jj = 0; jj < NFC; jj++) {
            int tv = sb[jj];
            if (tv < 8) {
                float w = sw2s[j * NFC + jj];
                switch (tv) {
                    case 0: O[0] += w; break;
                    case 1: O[1] += w; break;
                    case 2: O[2] += w; break;
                    case 3: O[3] += w; break;
                    case 4: O[4] += w; break;
                    case 5: O[5] += w; break;
                    case 6: O[6] += w; break;
                    case 7: O[7] += w; break;
                }
            }
        }
        float v = 0.f; int first = 8;
#pragma unroll
        for (int t = 0; t < TT; t++) {
            v += O[t];
            if (v >= 1.f) {
                v = 0.f;
                if (first == 8) first = t;
                atomicAdd(&sh4[t], 1);
            }
        }
        out[b * NOUT + j] = (first < 8) ? (float)(TT - first) / (float)TT : 0.f;
    }
    __syncthreads();
    if (tid < 8) {
        if (sh3[tid]) atomicAdd(&g_cnt3[tid], sh3[tid]);
        if (sh4[tid]) atomicAdd(&g_cnt4[tid], sh4[tid]);
    }
}

__global__ void k6_final(float* __restrict__ out, int write_reg) {
    if (threadIdx.x == 0 && write_reg) {
        float m1 = 0.f, m2 = 0.f, m3 = 0.f, m4 = 0.f;
        for (int t = 0; t < TT; t++) {
            m1 = fmaxf(m1, (float)g_cnt1[t] / (float)N1);
            m2 = fmaxf(m2, (float)g_cnt2[t] / (float)N1);
            m3 = fmaxf(m3, (float)g_cnt3[t] / (float)(BB * NFC));
            m4 = fmaxf(m4, (float)g_cnt4[t] / (float)(BB * NOUT));
        }
        out[BB * NOUT] = m1 + m2 + m3 + m4;
    }
}

extern "C" void kernel_launch(void* const* d_in, const int* in_sizes, int n_in,
                              void* d_out, int out_size) {
    const float* x  = (const float*)d_in[0];
    const float* ws = (const float*)d_in[1];
    const float* wc = (const float*)d_in[2];
    const float* w1 = (const float*)d_in[3];
    const float* w2 = (const float*)d_in[4];
    float* out = (float*)d_out;

    k_prep<<<(NT1P / 4 + 255) / 256, 256>>>(w1);
    k1_sconv<<<BB, 392>>>(x, ws);
    {
        dim3 g(BB, 2);
        k2_conv<<<g, 392>>>(wc);
    }
    k45<<<BB / 2, 512>>>(w2, out);
    k6_final<<<1, 1>>>(out, (out_size > BB * NOUT) ? 1 : 0);
}

// round 17
// speedup vs baseline: 1.1910x; 1.0822x over previous
#include <cuda_runtime.h>
#include <stdint.h>

#define BB 512
#define CH 16
#define HH 28
#define WW 28
#define HW 784
#define PH 14
#define PW 14
#define PHW 196
#define TT 8
#define NFC 100
#define NOUT 10
#define NPOOL (CH*PHW)  // 3136
#define NHALF (NPOOL/2) // 1568
#define N1 (BB*CH*HW)
#define PMAP 900        // padded 30x30 map
#define NT1P (BB*CH*PMAP)

typedef unsigned long long ull;

__device__ __align__(16) uint8_t g_t1p[NT1P];   // padded t1 maps, border=8
__device__ __align__(16) uint8_t g_tp[BB*NPOOL];
__device__ __align__(16) float   g_w1T[NPOOL*NFC];
__device__ int g_cnt1[9];
__device__ int g_cnt2[9];
__device__ int g_cnt3[9];
__device__ int g_cnt4[9];

// prep: zero counters + transpose w1 + prefill padded t1 maps with 8
__global__ void k_prep(const float* __restrict__ w1) {
    int idx = blockIdx.x * 256 + threadIdx.x;
    if (idx < 9) { g_cnt1[idx] = 0; g_cnt2[idx] = 0; g_cnt3[idx] = 0; g_cnt4[idx] = 0; }
    if (idx < NFC * NPOOL) {
        int j = idx / NPOOL;
        int n = idx - j * NPOOL;
        g_w1T[n * NFC + j] = w1[idx];
    }
    if (idx < NT1P / 4) ((uint32_t*)g_t1p)[idx] = 0x08080808u;
}

// packed 16-bit x4 histogram helpers (buckets 0..7; bucket 8 dropped)
__device__ __forceinline__ void hist_add(ull& h0, ull& h1, int t) {
    if (t < 8) {
        if (t < 4) h0 += 1ull << (16 * t);
        else       h1 += 1ull << (16 * (t - 4));
    }
}
__device__ __forceinline__ void hist_flush_warp(ull h0, ull h1, int tid, int* sh) {
    if (tid < (int)(blockDim.x & ~31u)) {
#pragma unroll
        for (int off = 16; off; off >>= 1) {
            h0 += __shfl_down_sync(0xffffffffu, h0, off);
            h1 += __shfl_down_sync(0xffffffffu, h1, off);
        }
        if ((tid & 31) == 0) {
#pragma unroll
            for (int t = 0; t < 4; t++) {
                int c0 = (int)((h0 >> (16 * t)) & 0xffff);
                int c1 = (int)((h1 >> (16 * t)) & 0xffff);
                if (c0) atomicAdd(&sh[t], c0);
                if (c1) atomicAdd(&sh[t + 4], c1);
            }
        }
    } else {
#pragma unroll
        for (int t = 0; t < 4; t++) {
            int c0 = (int)((h0 >> (16 * t)) & 0xffff);
            int c1 = (int)((h1 >> (16 * t)) & 0xffff);
            if (c0) atomicAdd(&sh[t], c0);
            if (c1) atomicAdd(&sh[t + 4], c1);
        }
    }
}

// Kernel 1 (frozen): static conv + OneSpikeIF t1, padded layout.
__global__ void __launch_bounds__(392) k1_sconv(const float* __restrict__ x,
                                                const float* __restrict__ ws) {
    int b = blockIdx.x;
    __shared__ float sx[900];
    __shared__ float sw[CH * 9];
    __shared__ int sh[8];
    int tid = threadIdx.x;
    uint8_t* outp = g_t1p + b * CH * PMAP;
    for (int i = tid; i < 900; i += 392) sx[i] = 0.f;
    for (int i = tid; i < CH * 9; i += 392) sw[i] = ws[i];
    if (tid < 8) sh[tid] = 0;
    __syncthreads();
    for (int i = tid; i < HW; i += 392) {
        int y = i / WW, xx = i - y * WW;
        sx[(y + 1) * 30 + xx + 1] = x[b * HW + i];
    }
    __syncthreads();
    ull h0 = 0, h1 = 0;
    for (int o = 0; o < CH; o++) {
        const float* w = sw + o * 9;
        for (int p = tid; p < HW; p += 392) {
            int y = p / WW, xx = p - y * WW;
            const float* xp = sx + (y + 1) * 30 + xx + 1;
            float acc = 0.f;
#pragma unroll
            for (int k = 0; k < 9; k++) {
                int dy = k / 3 - 1, dx = k % 3 - 1;
                acc += xp[dy * 30 + dx] * w[k];
            }
            float v = 0.f; int t1 = 8;
#pragma unroll
            for (int t = 0; t < TT; t++) { v += acc; if (v >= 1.f) { t1 = t; break; } }
            outp[o * PMAP + (y + 1) * 30 + xx + 1] = (uint8_t)t1;
            hist_add(h0, h1, t1);
        }
    }
    hist_flush_warp(h0, h1, tid, sh);
    __syncthreads();
    if (tid < 8 && sh[tid]) atomicAdd(&g_cnt1[tid], sh[tid]);
}

// one t-slice of a tap: 1 setp + 4 predicated packed FMAs (4 oc-pairs)
#define TAP8(TLIT, A0, A1, A2, A3, W0, W1, W2, W3, TV, ONE)            \
    asm("{.reg .pred p; setp.le.s32 p, %9, " TLIT ";\n\t"              \
        "@p fma.rn.f32x2 %0, %4, %8, %0;\n\t"                          \
        "@p fma.rn.f32x2 %1, %5, %8, %1;\n\t"                          \
        "@p fma.rn.f32x2 %2, %6, %8, %2;\n\t"                          \
        "@p fma.rn.f32x2 %3, %7, %8, %3;}\n\t"                         \
        : "+l"(A0), "+l"(A1), "+l"(A2), "+l"(A3)                       \
        : "l"(W0), "l"(W1), "l"(W2), "l"(W3), "l"(ONE), "r"(TV))

#define TAP8U(A0, A1, A2, A3, W0, W1, W2, W3, ONE)                     \
    asm("fma.rn.f32x2 %0, %4, %8, %0;\n\t"                             \
        "fma.rn.f32x2 %1, %5, %8, %1;\n\t"                             \
        "fma.rn.f32x2 %2, %6, %8, %2;\n\t"                             \
        "fma.rn.f32x2 %3, %7, %8, %3;"                                 \
        : "+l"(A0), "+l"(A1), "+l"(A2), "+l"(A3)                       \
        : "l"(W0), "l"(W1), "l"(W2), "l"(W3), "l"(ONE))

// pass A tap: early taps (tv<4) -> slices 0..3 (slice 3 unconditional)
#define DO_TAP_A(TV, WP)                                                    \
    if ((TV) < 4) {                                                         \
        const ulonglong2* _w = (const ulonglong2*)(WP);                     \
        ulonglong2 _wa = _w[0], _wb = _w[1];                                \
        TAP8("0", a0[0], a1[0], a2[0], a3[0], _wa.x, _wa.y, _wb.x, _wb.y, TV, ONE); \
        TAP8("1", a0[1], a1[1], a2[1], a3[1], _wa.x, _wa.y, _wb.x, _wb.y, TV, ONE); \
        TAP8("2", a0[2], a1[2], a2[2], a3[2], _wa.x, _wa.y, _wb.x, _wb.y, TV, ONE); \
        TAP8U(     a0[3], a1[3], a2[3], a3[3], _wa.x, _wa.y, _wb.x, _wb.y, ONE);    \
    }

// pass B tap: LATE taps only (4<=tv<8) -> windowed sums atop the A[3] carry.
// Early taps are already inside the carry; letting them through would double-count.
#define DO_TAP_B(TV, WP)                                                    \
    if ((unsigned)((TV) - 4) < 4u) {                                        \
        const ulonglong2* _w = (const ulonglong2*)(WP);                     \
        ulonglong2 _wa = _w[0], _wb = _w[1];                                \
        TAP8("4", a0[0], a1[0], a2[0], a3[0], _wa.x, _wa.y, _wb.x, _wb.y, TV, ONE); \
        TAP8("5", a0[1], a1[1], a2[1], a3[1], _wa.x, _wa.y, _wb.x, _wb.y, TV, ONE); \
        TAP8("6", a0[2], a1[2], a2[2], a3[2], _wa.x, _wa.y, _wb.x, _wb.y, TV, ONE); \
        TAP8U(     a0[3], a1[3], a2[3], a3[3], _wa.x, _wa.y, _wb.x, _wb.y, ONE);    \
    }

#define DO_ROW_A(RO, WROW) do {                                             \
    int tv0 = tp[(RO) - 1], tv1 = tp[(RO)], tv2 = tp[(RO) + 1];             \
    DO_TAP_A(tv0, (WROW) + 0);                                              \
    DO_TAP_A(tv1, (WROW) + 8);                                              \
    DO_TAP_A(tv2, (WROW) + 16);                                             \
} while (0)

#define DO_ROW_B(RO, WROW) do {                                             \
    int tv0 = tp[(RO) - 1], tv1 = tp[(RO)], tv2 = tp[(RO) + 1];             \
    DO_TAP_B(tv0, (WROW) + 0);                                              \
    DO_TAP_B(tv1, (WROW) + 8);                                              \
    DO_TAP_B(tv2, (WROW) + 16);                                             \
} while (0)

#define EXTA(ARR, PR) do {                                                  \
    int lo = 8, hi = 8;                                                     \
    _Pragma("unroll")                                                       \
    for (int t = 3; t >= 0; t--) {                                          \
        ull v = ARR[t];                                                     \
        if (__uint_as_float((uint32_t)v) >= 1.f) lo = t;                    \
        if (__uint_as_float((uint32_t)(v >> 32)) >= 1.f) hi = t;            \
    }                                                                       \
    t2a_pack |= ((uint32_t)lo << (8 * (PR))) | ((uint32_t)hi << (8 * (PR) + 4)); \
} while (0)

#define EXTB(ARR, PR) do {                                                  \
    int lo = 8, hi = 8;                                                     \
    _Pragma("unroll")                                                       \
    for (int s = 3; s >= 0; s--) {                                          \
        ull v = ARR[s];                                                     \
        if (__uint_as_float((uint32_t)v) >= 1.f) lo = s + 4;                \
        if (__uint_as_float((uint32_t)(v >> 32)) >= 1.f) hi = s + 4;        \
    }                                                                       \
    int ta = (t2a_pack >> (8 * (PR))) & 15;                                 \
    int tb = (t2a_pack >> (8 * (PR) + 4)) & 15;                             \
    int flo = (ta < 8) ? ta : lo;                                           \
    int fhi = (tb < 8) ? tb : hi;                                           \
    int o = half * 8 + (PR) * 2;                                            \
    s2[o * 392 + tid] = (uint8_t)flo;       hist_add(h0, h1, flo);          \
    s2[(o + 1) * 392 + tid] = (uint8_t)fhi; hist_add(h0, h1, fhi);          \
} while (0)

// Kernel 2: conv2 all 8 timesteps, fused pool. t-split with carry:
// pass A = early taps (tv<4) -> A[0..3]; pass B = LATE taps only, seeded A[3].
__global__ void __launch_bounds__(392, 2) k2_conv(const float* __restrict__ wc) {
    int b = blockIdx.x;
    int tid = threadIdx.x;
    int p = blockIdx.y * 392 + tid;
    __shared__ __align__(16) uint8_t st[CH * PMAP];
    __shared__ __align__(16) ull sw2[CH * 9 * 8];
    __shared__ uint8_t s2[CH * 392];
    __shared__ uint32_t sfm[CH * 30];    // fired (<8) bitmap per (ic,row)
    __shared__ uint32_t sfm4[CH * 30];   // early-fired (<4) bitmap
    __shared__ int sh[8];

    if (tid < 8) sh[tid] = 0;
    {
        const uint4* src = (const uint4*)(g_t1p + b * CH * PMAP);
        uint4* dst = (uint4*)st;
        for (int i = tid; i < CH * PMAP / 16; i += 392) dst[i] = src[i];
    }
    for (int idx = tid; idx < CH * 9 * 8; idx += 392) {
        int pr = idx & 7;
        int ik = idx >> 3;
        uint32_t lo = __float_as_uint(wc[(2 * pr) * (CH * 9) + ik]);
        uint32_t hi = __float_as_uint(wc[(2 * pr + 1) * (CH * 9) + ik]);
        sw2[idx] = ((ull)hi << 32) | lo;
    }
    __syncthreads();
    for (int idx = tid; idx < CH * 30; idx += 392) {
        const uint8_t* row = st + (idx / 30) * PMAP + (idx % 30) * 30;
        uint32_t m8 = 0, m4 = 0;
#pragma unroll
        for (int c = 0; c < 30; c++) {
            int v = row[c];
            m8 |= (v < 8 ? 1u : 0u) << c;
            m4 |= (v < 4 ? 1u : 0u) << c;
        }
        sfm[idx] = m8;
        sfm4[idx] = m4;
    }
    __syncthreads();

    int y = p / WW, x = p - y * WW;
    const int q = (y + 1) * 30 + (x + 1);
    const ull ONE = 0x3f8000003f800000ull;
    ull h0 = 0, h1 = 0;

    // rowmasks: rm4 = rows with early taps, rm48 = rows with late taps
    ull rm4 = 0, rm48 = 0;
#pragma unroll
    for (int i = 0; i < CH; i++) {
        uint32_t f0 = (sfm[i * 30 + y]     >> x) & 7u;
        uint32_t f1 = (sfm[i * 30 + y + 1] >> x) & 7u;
        uint32_t f2 = (sfm[i * 30 + y + 2] >> x) & 7u;
        uint32_t e0 = (sfm4[i * 30 + y]     >> x) & 7u;
        uint32_t e1 = (sfm4[i * 30 + y + 1] >> x) & 7u;
        uint32_t e2 = (sfm4[i * 30 + y + 2] >> x) & 7u;
        rm4  |= (ull)((e0 ? 1u : 0u) | (e1 ? 2u : 0u) | (e2 ? 4u : 0u)) << (3 * i);
        uint32_t l0 = f0 & ~e0, l1 = f1 & ~e1, l2 = f2 & ~e2;
        rm48 |= (ull)((l0 ? 1u : 0u) | (l1 ? 2u : 0u) | (l2 ? 4u : 0u)) << (3 * i);
    }

    const unsigned am = (tid >= 384) ? 0x000000ffu : 0xffffffffu;
    if (__all_sync(am, (rm4 | rm48) == 0ull)) {
#pragma unroll
        for (int o = 0; o < CH; o++) s2[o * 392 + tid] = 8;
    } else {
        for (int half = 0; half < 2; half++) {
            uint32_t t2a_pack = 0;
            ull c0, c1, c2, c3;   // carry = A[3] per oc-pair
            {   // pass A: slices t=0..3, early taps (tv<4) only
                ull a0[4], a1[4], a2[4], a3[4];
#pragma unroll
                for (int s = 0; s < 4; s++) { a0[s] = 0; a1[s] = 0; a2[s] = 0; a3[s] = 0; }
#pragma unroll 1
                for (int i = 0; i < CH; i++) {
                    unsigned g = (unsigned)(rm4 >> (3 * i)) & 7u;
                    if (!g) continue;
                    const uint8_t* tp = st + i * PMAP + q;
                    const ull* wi = sw2 + i * 72 + half * 4;
                    if (g & 1u) DO_ROW_A(-30, wi + 0);
                    if (g & 2u) DO_ROW_A(0,   wi + 24);
                    if (g & 4u) DO_ROW_A(30,  wi + 48);
                }
                EXTA(a0, 0); EXTA(a1, 1); EXTA(a2, 2); EXTA(a3, 3);
                c0 = a0[3]; c1 = a1[3]; c2 = a2[3]; c3 = a3[3];
            }
            {   // pass B: slices t=4..7 = carry + late taps (4<=tv<8)
                ull a0[4], a1[4], a2[4], a3[4];
#pragma unroll
                for (int s = 0; s < 4; s++) { a0[s] = c0; a1[s] = c1; a2[s] = c2; a3[s] = c3; }
#pragma unroll 1
                for (int i = 0; i < CH; i++) {
                    unsigned g = (unsigned)(rm48 >> (3 * i)) & 7u;
                    if (!g) continue;
                    const uint8_t* tp = st + i * PMAP + q;
                    const ull* wi = sw2 + i * 72 + half * 4;
                    if (g & 1u) DO_ROW_B(-30, wi + 0);
                    if (g & 2u) DO_ROW_B(0,   wi + 24);
                    if (g & 4u) DO_ROW_B(30,  wi + 48);
                }
                EXTB(a0, 0); EXTB(a1, 1); EXTB(a2, 2); EXTB(a3, 3);
            }
        }
    }
    hist_flush_warp(h0, h1, tid, sh);
    __syncthreads();
    for (int idx = tid; idx < CH * 7 * PW; idx += 392) {
        int X = idx % PW;
        int r = idx / PW;
        int Yl = r % 7;
        int oc = r / 7;
        const uint8_t* base = s2 + oc * 392 + (Yl * 2) * WW + X * 2;
        int m = min(min((int)base[0], (int)base[1]),
                    min((int)base[WW], (int)base[WW + 1]));
        g_tp[b * NPOOL + oc * PHW + (blockIdx.y * 7 + Yl) * PW + X] = (uint8_t)m;
    }
    if (tid < 8 && sh[tid]) atomicAdd(&g_cnt2[tid], sh[tid]);
}

// Kernel 45: 2 batches x 2 n-halves per 512-thread block; intra-group 8-skips.
__global__ void __launch_bounds__(512) k45(const float* __restrict__ w2,
                                           float* __restrict__ out) {
    const ull K8 = 0x0808080808080808ull;
    int b0 = blockIdx.x * 2;
    int tid = threadIdx.x;
    int bb = tid >> 8;
    int half = (tid >> 7) & 1;
    int j = tid & 127;
    __shared__ uint8_t stp[2 * NPOOL];
    __shared__ float sw2s[NOUT * NFC];
    __shared__ float sS[2][NFC][8];
    __shared__ uint8_t s3[2 * NFC];
    __shared__ int sh3[8], sh4[8];
    {
        const uint4* src = (const uint4*)(g_tp + b0 * NPOOL);
        for (int i = tid; i < 2 * NPOOL / 16; i += 512) ((uint4*)stp)[i] = src[i];
    }
    for (int i = tid; i < NOUT * NFC; i += 512) sw2s[i] = w2[i];
    if (tid < 8) { sh3[tid] = 0; sh4[tid] = 0; }
    __syncthreads();

    float S[8] = {0.f, 0.f, 0.f, 0.f, 0.f, 0.f, 0.f, 0.f};
    if (j < NFC) {
        const uint8_t* tb = stp + bb * NPOOL;
        const int nbeg = half * NHALF, nend = nbeg + NHALF;
        const float* wcol = g_w1T + j;
#pragma unroll 1
        for (int n0 = nbeg; n0 < nend; n0 += 8) {
            ull tvA = *(const ull*)(tb + n0);
            if (tvA == K8) continue;              // 8-group unfired: exact skip
            float w[8];                            // 8 independent loads in flight
#pragma unroll
            for (int i = 0; i < 8; i++) w[i] = __ldg(wcol + (n0 + i) * NFC);
#pragma unroll
            for (int i = 0; i < 8; i++) {
                int tv = (int)((tvA >> (8 * i)) & 0xff);
                if (tv < 8) {                     // uniform across warp
                    switch (tv) {                 // uniform switch, one FADD
                        case 0: S[0] += w[i]; break;
                        case 1: S[1] += w[i]; break;
                        case 2: S[2] += w[i]; break;
                        case 3: S[3] += w[i]; break;
                        case 4: S[4] += w[i]; break;
                        case 5: S[5] += w[i]; break;
                        case 6: S[6] += w[i]; break;
                        case 7: S[7] += w[i]; break;
                    }
                }
            }
        }
    }
    if (half == 1 && j < NFC) {
#pragma unroll
        for (int t = 0; t < 8; t++) sS[bb][j][t] = S[t];
    }
    __syncthreads();
    int t3 = 8;
    if (half == 0 && j < NFC) {
        float Cv = 0.f;
#pragma unroll
        for (int t = 0; t < TT; t++) {
            Cv += S[t] + sS[bb][j][t];
            if (t3 == 8 && Cv >= 1.f) t3 = t;
        }
        s3[bb * NFC + j] = (uint8_t)t3;
    }
    if (half == 0) {
#pragma unroll
        for (int t = 0; t < 8; t++) {
            unsigned bal = __ballot_sync(0xffffffffu, (j < NFC) && (t3 == t));
            if ((tid & 31) == 0 && bal) atomicAdd(&sh3[t], __popc(bal));
        }
    }
    __syncthreads();
    if (half == 0 && j < NOUT) {
        int b = b0 + bb;
        const uint8_t* sb = s3 + bb * NFC;
        float O[8] = {0.f, 0.f, 0.f, 0.f, 0.f, 0.f, 0.f, 0.f};
        for (int jj = 0; jj < NFC; jj++) {
            int tv = sb[jj];
            if (tv < 8) {
                float w = sw2s[j * NFC + jj];
                switch (tv) {
                    case 0: O[0] += w; break;
                    case 1: O[1] += w; break;
                    case 2: O[2] += w; break;
                    case 3: O[3] += w; break;
                    case 4: O[4] += w; break;
                    case 5: O[5] += w; break;
                    case 6: O[6] += w; break;
                    case 7: O[7] += w; break;
                }
            }
        }
        float v = 0.f; int first = 8;
#pragma unroll
        for (int t = 0; t < TT; t++) {
            v += O[t];
            if (v >= 1.f) {
                v = 0.f;
                if (first == 8) first = t;
                atomicAdd(&sh4[t], 1);
            }
        }
        out[b * NOUT + j] = (first < 8) ? (float)(TT - first) / (float)TT : 0.f;
    }
    __syncthreads();
    if (tid < 8) {
        if (sh3[tid]) atomicAdd(&g_cnt3[tid], sh3[tid]);
        if (sh4[tid]) atomicAdd(&g_cnt4[tid], sh4[tid]);
    }
}

__global__ void k6_final(float* __restrict__ out, int write_reg) {
    if (threadIdx.x == 0 && write_reg) {
        float m1 = 0.f, m2 = 0.f, m3 = 0.f, m4 = 0.f;
        for (int t = 0; t < TT; t++) {
            m1 = fmaxf(m1, (float)g_cnt1[t] / (float)N1);
            m2 = fmaxf(m2, (float)g_cnt2[t] / (float)N1);
            m3 = fmaxf(m3, (float)g_cnt3[t] / (float)(BB * NFC));
            m4 = fmaxf(m4, (float)g_cnt4[t] / (float)(BB * NOUT));
        }
        out[BB * NOUT] = m1 + m2 + m3 + m4;
    }
}

extern "C" void kernel_launch(void* const* d_in, const int* in_sizes, int n_in,
                              void* d_out, int out_size) {
    const float* x  = (const float*)d_in[0];
    const float* ws = (const float*)d_in[1];
    const float* wc = (const float*)d_in[2];
    const float* w1 = (const float*)d_in[3];
    const float* w2 = (const float*)d_in[4];
    float* out = (float*)d_out;

    k_prep<<<(NT1P / 4 + 255) / 256, 256>>>(w1);
    k1_sconv<<<BB, 392>>>(x, ws);
    {
        dim3 g(BB, 2);
        k2_conv<<<g, 392>>>(wc);
    }
    k45<<<BB / 2, 512>>>(w2, out);
    k6_final<<<1, 1>>>(out, (out_size > BB * NOUT) ? 1 : 0);
}